// round 1
// baseline (speedup 1.0000x reference)
#include <cuda_runtime.h>

// Problem constants
#define BB 8
#define CC 32
#define PP 128
#define DD 256
#define HH 8
#define RR 32
#define NT (BB*CC)        // 256 time sequences, len PP
#define NC (BB*PP)        // 1024 chan sequences, len CC
#define ROWS 32768        // NT*PP == NC*CC
#define OUT_HALF (BB*CC*PP*DD)   // 8388608

// ---------------- scratch (device globals; no allocation allowed) ----------
__device__ float d_raw_t[ROWS*512];
__device__ float d_raw_c[ROWS*512];
__device__ float d_qur_t[NT*HH*PP*RR];
__device__ float d_quo_t[NT*HH*PP*RR];
__device__ float d_qvr_t[NT*HH*PP*RR];
__device__ float d_qur_c[NC*HH*CC*RR];
__device__ float d_quo_c[NC*HH*CC*RR];
__device__ float d_qvr_c[NC*HH*CC*RR];
__device__ float d_F_t[NT*HH*PP*PP];     // logits then qh_t (in place)
__device__ float d_F_c[NC*HH*CC*CC];     // logits then qh_c
__device__ float d_g1_t[ROWS*DD];
__device__ float d_g2_t[ROWS*DD];
__device__ float d_g1_c[ROWS*DD];
__device__ float d_g2_c[ROWS*DD];
__device__ float d_cos[PP*16];
__device__ float d_sin[PP*16];

// ---------------- rope table ----------------
__global__ void k_setup() {
    int idx = blockIdx.x * blockDim.x + threadIdx.x;
    if (idx < PP*16) {
        int s = idx >> 4, i = idx & 15;
        double invf = pow(10000.0, -((double)(2*i)) / 32.0);
        double a = (double)s * invf;
        d_cos[idx] = (float)cos(a);
        d_sin[idx] = (float)sin(a);
    }
}

// ---------------- proj GEMM: C[32768,512] = A @ [u|v]^T -------------------
// gather=0: A row i = qz row i (time). gather=1: channel permutation.
__global__ __launch_bounds__(256) void k_proj(const float* __restrict__ A,
                                              const float* __restrict__ U,
                                              const float* __restrict__ V,
                                              int gather)
{
    __shared__ float As[16][132];
    __shared__ float Bs[16][132];
    float* Craw = gather ? d_raw_c : d_raw_t;
    const int tid = threadIdx.x;
    const int m0 = blockIdx.y * 128;
    const int n0 = blockIdx.x * 128;
    const int tx = tid & 15, ty = tid >> 4;
    float acc[8][8];
#pragma unroll
    for (int i = 0; i < 8; i++)
#pragma unroll
        for (int j = 0; j < 8; j++) acc[i][j] = 0.f;

    int arow[2];
    const float* wp[2];
#pragma unroll
    for (int l = 0; l < 2; l++) {
        int lin = tid + l*256;
        int r = lin >> 2;
        int grow = m0 + r;
        if (gather) {
            int b = grow >> 12, rem = grow & 4095;
            int p = rem >> 5, c = rem & 31;
            arow[l] = ((b << 5) + c) * 128 + p;
        } else arow[l] = grow;
        int gj = n0 + r;
        wp[l] = (gj < 256) ? (U + gj*256) : (V + (gj - 256)*256);
    }

    for (int k0 = 0; k0 < 256; k0 += 16) {
#pragma unroll
        for (int l = 0; l < 2; l++) {
            int lin = tid + l*256;
            int r = lin >> 2;
            int kq = (lin & 3) << 2;
            float4 a = *reinterpret_cast<const float4*>(&A[arow[l]*256 + k0 + kq]);
            As[kq  ][r] = a.x; As[kq+1][r] = a.y; As[kq+2][r] = a.z; As[kq+3][r] = a.w;
            float4 w = *reinterpret_cast<const float4*>(wp[l] + k0 + kq);
            Bs[kq  ][r] = w.x; Bs[kq+1][r] = w.y; Bs[kq+2][r] = w.z; Bs[kq+3][r] = w.w;
        }
        __syncthreads();
#pragma unroll
        for (int k = 0; k < 16; k++) {
            float a[8], b[8];
            *(float4*)&a[0] = *(const float4*)&As[k][ty*8];
            *(float4*)&a[4] = *(const float4*)&As[k][ty*8+4];
            *(float4*)&b[0] = *(const float4*)&Bs[k][tx*8];
            *(float4*)&b[4] = *(const float4*)&Bs[k][tx*8+4];
#pragma unroll
            for (int i = 0; i < 8; i++)
#pragma unroll
                for (int j = 0; j < 8; j++) acc[i][j] += a[i]*b[j];
        }
        __syncthreads();
    }
#pragma unroll
    for (int i = 0; i < 8; i++) {
        int row = m0 + ty*8 + i;
#pragma unroll
        for (int j4 = 0; j4 < 2; j4++) {
            float4 v;
            v.x = acc[i][j4*4]; v.y = acc[i][j4*4+1];
            v.z = acc[i][j4*4+2]; v.w = acc[i][j4*4+3];
            *reinterpret_cast<float4*>(&Craw[(long long)row*512 + n0 + tx*8 + j4*4]) = v;
        }
    }
}

// ---------------- RoPE: raw qu|qv -> qur, quo, qvr in [n,h,s,r] -----------
__global__ __launch_bounds__(256) void k_rope(int branch /*0=time,1=chan*/)
{
    const float* raw = branch ? d_raw_c : d_raw_t;
    float* qur = branch ? d_qur_c : d_qur_t;
    float* quo = branch ? d_quo_c : d_quo_t;
    float* qvr = branch ? d_qvr_c : d_qvr_t;
    int Sbits = branch ? 5 : 7;

    int warp = threadIdx.x >> 5, lane = threadIdx.x & 31;
    int task = blockIdx.x * 8 + warp;      // row*8 + h
    int h = task & 7;
    int row = task >> 3;
    int S = 1 << Sbits;
    int s = row & (S - 1);
    int n = row >> Sbits;

    float qu = raw[(long long)row*512 + h*32 + lane];
    float qv = raw[(long long)row*512 + 256 + h*32 + lane];
    float c  = d_cos[s*16 + (lane & 15)];
    float sn = d_sin[s*16 + (lane & 15)];
    float pu = __shfl_xor_sync(0xffffffffu, qu, 16);
    float pv = __shfl_xor_sync(0xffffffffu, qv, 16);
    float sgn = (lane < 16) ? -1.f : 1.f;
    int ob = ((n*8 + h)*S + s)*32 + lane;
    qur[ob] = qu*c + sgn*pu*sn;   // apply
    quo[ob] = qu*c - sgn*pu*sn;   // apply_o
    qvr[ob] = qv*c + sgn*pv*sn;   // apply
}

// ---------------- F_t: per (n,h) 128x128 = qur @ qvr^T + mask -------------
__global__ __launch_bounds__(256) void k_ft(const float* __restrict__ mask)
{
    __shared__ float SuT[32][132];
    __shared__ float SvT[32][132];
    int nh = blockIdx.x;
    int n = nh >> 3;
    const float* ubase = d_qur_t + nh*128*32;
    const float* vbase = d_qvr_t + nh*128*32;
    int tid = threadIdx.x;
#pragma unroll
    for (int l = 0; l < 4; l++) {
        int lin = tid + l*256;
        int s = lin >> 3, rq = (lin & 7) << 2;
        float4 u = *reinterpret_cast<const float4*>(ubase + s*32 + rq);
        SuT[rq][s] = u.x; SuT[rq+1][s] = u.y; SuT[rq+2][s] = u.z; SuT[rq+3][s] = u.w;
        float4 v = *reinterpret_cast<const float4*>(vbase + s*32 + rq);
        SvT[rq][s] = v.x; SvT[rq+1][s] = v.y; SvT[rq+2][s] = v.z; SvT[rq+3][s] = v.w;
    }
    __syncthreads();
    int tx = tid & 15, ty = tid >> 4;
    float acc[8][8];
#pragma unroll
    for (int i = 0; i < 8; i++)
#pragma unroll
        for (int j = 0; j < 8; j++) acc[i][j] = 0.f;
#pragma unroll
    for (int k = 0; k < 32; k++) {
        float a[8], b[8];
        *(float4*)&a[0] = *(const float4*)&SuT[k][ty*8];
        *(float4*)&a[4] = *(const float4*)&SuT[k][ty*8+4];
        *(float4*)&b[0] = *(const float4*)&SvT[k][tx*8];
        *(float4*)&b[4] = *(const float4*)&SvT[k][tx*8+4];
#pragma unroll
        for (int i = 0; i < 8; i++)
#pragma unroll
            for (int j = 0; j < 8; j++) acc[i][j] += a[i]*b[j];
    }
    float* fout = d_F_t + (long long)nh*16384;
    const float* mrow = mask + (long long)n*16384;
#pragma unroll
    for (int i = 0; i < 8; i++) {
        int s = ty*8 + i;
#pragma unroll
        for (int j4 = 0; j4 < 2; j4++) {
            int t = tx*8 + j4*4;
            float4 m4 = *reinterpret_cast<const float4*>(mrow + s*128 + t);
            float4 o;
            o.x = acc[i][j4*4]   + m4.x;
            o.y = acc[i][j4*4+1] + m4.y;
            o.z = acc[i][j4*4+2] + m4.z;
            o.w = acc[i][j4*4+3] + m4.w;
            *reinterpret_cast<float4*>(fout + s*128 + t) = o;
        }
    }
}

// ---------------- F_c: per (n,h) 32x32 = qur @ qvr^T + mask ---------------
__global__ __launch_bounds__(256) void k_fc(const float* __restrict__ mask)
{
    __shared__ float SuT[32][36];
    __shared__ float SvT[32][36];
    int nh = blockIdx.x;
    int n = nh >> 3;
    const float* ubase = d_qur_c + nh*1024;
    const float* vbase = d_qvr_c + nh*1024;
    int tid = threadIdx.x;
    {
        int s = tid >> 3, rq = (tid & 7) << 2;
        float4 u = *reinterpret_cast<const float4*>(ubase + s*32 + rq);
        SuT[rq][s] = u.x; SuT[rq+1][s] = u.y; SuT[rq+2][s] = u.z; SuT[rq+3][s] = u.w;
        float4 v = *reinterpret_cast<const float4*>(vbase + s*32 + rq);
        SvT[rq][s] = v.x; SvT[rq+1][s] = v.y; SvT[rq+2][s] = v.z; SvT[rq+3][s] = v.w;
    }
    __syncthreads();
    int tx = tid & 7, ty = tid >> 3;   // s = ty, t0 = tx*4
    float acc[4] = {0.f, 0.f, 0.f, 0.f};
#pragma unroll
    for (int k = 0; k < 32; k++) {
        float a = SuT[k][ty];
        float4 b = *(const float4*)&SvT[k][tx*4];
        acc[0] += a*b.x; acc[1] += a*b.y; acc[2] += a*b.z; acc[3] += a*b.w;
    }
    int t0 = tx*4;
    float4 m4 = *reinterpret_cast<const float4*>(mask + (long long)n*1024 + ty*32 + t0);
    float4 o;
    o.x = acc[0] + m4.x; o.y = acc[1] + m4.y; o.z = acc[2] + m4.z; o.w = acc[3] + m4.w;
    *reinterpret_cast<float4*>(d_F_c + (long long)nh*1024 + ty*32 + t0) = o;
}

// ---------------- joint softmax over 128+32 candidates (warp/row) ---------
__global__ __launch_bounds__(256) void k_softmax()
{
    int warp = threadIdx.x >> 5, lane = threadIdx.x & 31;
    int rowid = blockIdx.x * 8 + warp;    // ((b*8+h)*32 + c)*128 + p
    int p  = rowid & 127;
    int r1 = rowid >> 7;
    int c  = r1 & 31;
    int r2 = r1 >> 5;
    int h  = r2 & 7;
    int b  = r2 >> 3;
    float* ft = d_F_t + ((long long)(((b*32 + c)*8 + h)*128 + p))*128;
    float* fc = d_F_c + ((long long)(((b*128 + p)*8 + h)*32 + c))*32;
    float v[5];
    v[0] = ft[lane]; v[1] = ft[lane+32]; v[2] = ft[lane+64]; v[3] = ft[lane+96];
    v[4] = fc[lane];
    float m = v[0];
#pragma unroll
    for (int i = 1; i < 5; i++) m = fmaxf(m, v[i]);
#pragma unroll
    for (int off = 16; off >= 1; off >>= 1)
        m = fmaxf(m, __shfl_xor_sync(0xffffffffu, m, off));
    float sum = 0.f;
#pragma unroll
    for (int i = 0; i < 5; i++) { v[i] = expf(256.f*(v[i] - m)); sum += v[i]; }
#pragma unroll
    for (int off = 16; off >= 1; off >>= 1)
        sum += __shfl_xor_sync(0xffffffffu, sum, off);
    float inv = 1.f / sum;
    ft[lane]     = v[0]*inv;
    ft[lane+32]  = v[1]*inv;
    ft[lane+64]  = v[2]*inv;
    ft[lane+96]  = v[3]*inv;
    fc[lane]     = v[4]*inv;
}

// ---------------- G time: A1 = qh@qvr, A2 = qh^T@quo, rope, -> [n,s,d] ----
__global__ __launch_bounds__(256) void k_gt()
{
    __shared__ float Qa[32][132];   // Qa[i][s] = qh[s][t0+i]
    __shared__ float Qb[32][132];   // Qb[i][s] = qh[t0+i][s]
    __shared__ float Vs[32][34];
    __shared__ float Us[32][34];
    int nh = blockIdx.x;
    int n = nh >> 3, h = nh & 7;
    const float* qh = d_F_t + (long long)nh*16384;
    const float* vb = d_qvr_t + nh*4096;
    const float* ub = d_quo_t + nh*4096;
    int tid = threadIdx.x;
    int rg = tid & 7, sg = tid >> 3;   // s = sg*4+si, r = rg*2 + {0,1,16,17}
    float a1[4][4], a2[4][4];
#pragma unroll
    for (int i = 0; i < 4; i++)
#pragma unroll
        for (int j = 0; j < 4; j++) { a1[i][j] = 0.f; a2[i][j] = 0.f; }

    for (int t0 = 0; t0 < 128; t0 += 32) {
        __syncthreads();
#pragma unroll
        for (int l = 0; l < 4; l++) {
            int lin = tid + l*256;
            int s = lin >> 3, iq = (lin & 7) << 2;
            float4 q = *(const float4*)(qh + s*128 + t0 + iq);
            Qa[iq][s] = q.x; Qa[iq+1][s] = q.y; Qa[iq+2][s] = q.z; Qa[iq+3][s] = q.w;
        }
#pragma unroll
        for (int l = 0; l < 4; l++) {
            int lin = tid + l*256;
            int i = lin >> 5, sq = (lin & 31) << 2;
            float4 q = *(const float4*)(qh + (t0 + i)*128 + sq);
            *(float4*)&Qb[i][sq] = q;
        }
        {
            int i = tid >> 3, rq = (tid & 7) << 2;
            float4 v = *(const float4*)(vb + (t0 + i)*32 + rq);
            Vs[i][rq] = v.x; Vs[i][rq+1] = v.y; Vs[i][rq+2] = v.z; Vs[i][rq+3] = v.w;
            float4 u = *(const float4*)(ub + (t0 + i)*32 + rq);
            Us[i][rq] = u.x; Us[i][rq+1] = u.y; Us[i][rq+2] = u.z; Us[i][rq+3] = u.w;
        }
        __syncthreads();
#pragma unroll
        for (int i = 0; i < 32; i++) {
            float4 qa = *(const float4*)&Qa[i][sg*4];
            float4 qb = *(const float4*)&Qb[i][sg*4];
            float2 v0 = *(const float2*)&Vs[i][rg*2];
            float2 v1 = *(const float2*)&Vs[i][rg*2+16];
            float2 u0 = *(const float2*)&Us[i][rg*2];
            float2 u1 = *(const float2*)&Us[i][rg*2+16];
            float av[4] = {qa.x, qa.y, qa.z, qa.w};
            float bv[4] = {qb.x, qb.y, qb.z, qb.w};
            float vv[4] = {v0.x, v0.y, v1.x, v1.y};
            float uv[4] = {u0.x, u0.y, u1.x, u1.y};
#pragma unroll
            for (int si = 0; si < 4; si++)
#pragma unroll
                for (int rj = 0; rj < 4; rj++) {
                    a1[si][rj] += av[si]*vv[rj];
                    a2[si][rj] += bv[si]*uv[rj];
                }
        }
    }
#pragma unroll
    for (int si = 0; si < 4; si++) {
        int s = sg*4 + si;
#pragma unroll
        for (int rj = 0; rj < 2; rj++) {
            int r = rg*2 + rj;              // r < 16
            float c  = d_cos[s*16 + r];
            float sn = d_sin[s*16 + r];
            float xl = a1[si][rj], xh = a1[si][rj+2];
            float yl = a2[si][rj], yh = a2[si][rj+2];
            int ob = (n*128 + s)*256 + h*32 + r;
            d_g1_t[ob]    = xl*c + xh*sn;   // apply_o lo
            d_g1_t[ob+16] = xh*c - xl*sn;   // apply_o hi
            d_g2_t[ob]    = yl*c - yh*sn;   // apply lo
            d_g2_t[ob+16] = yh*c + yl*sn;   // apply hi
        }
    }
}

// ---------------- G chan: 32x32 versions ----------------------------------
__global__ __launch_bounds__(128) void k_gc()
{
    __shared__ float Qn[32][34];
    __shared__ float Vs[32][34];
    __shared__ float Us[32][34];
    int nh = blockIdx.x;
    int n = nh >> 3, h = nh & 7;
    const float* qh = d_F_c + (long long)nh*1024;
    const float* vb = d_qvr_c + nh*1024;
    const float* ub = d_quo_c + nh*1024;
    int tid = threadIdx.x;
#pragma unroll
    for (int l = 0; l < 2; l++) {
        int lin = tid + l*128;
        int t = lin >> 3, sq = (lin & 7) << 2;
        float4 q = *(const float4*)(qh + t*32 + sq);
        Qn[t][sq] = q.x; Qn[t][sq+1] = q.y; Qn[t][sq+2] = q.z; Qn[t][sq+3] = q.w;
        float4 v = *(const float4*)(vb + t*32 + sq);
        Vs[t][sq] = v.x; Vs[t][sq+1] = v.y; Vs[t][sq+2] = v.z; Vs[t][sq+3] = v.w;
        float4 u = *(const float4*)(ub + t*32 + sq);
        Us[t][sq] = u.x; Us[t][sq+1] = u.y; Us[t][sq+2] = u.z; Us[t][sq+3] = u.w;
    }
    __syncthreads();
    int rg = tid & 7, sg = tid >> 3;    // s = sg*2 + si
    float a1[2][4], a2[2][4];
#pragma unroll
    for (int i = 0; i < 2; i++)
#pragma unroll
        for (int j = 0; j < 4; j++) { a1[i][j] = 0.f; a2[i][j] = 0.f; }
#pragma unroll
    for (int t = 0; t < 32; t++) {
        float av[2];
        av[0] = Qn[sg*2][t];
        av[1] = Qn[sg*2+1][t];
        float2 qb = *(const float2*)&Qn[t][sg*2];
        float2 v0 = *(const float2*)&Vs[t][rg*2];
        float2 v1 = *(const float2*)&Vs[t][rg*2+16];
        float2 u0 = *(const float2*)&Us[t][rg*2];
        float2 u1 = *(const float2*)&Us[t][rg*2+16];
        float bv[2] = {qb.x, qb.y};
        float vv[4] = {v0.x, v0.y, v1.x, v1.y};
        float uv[4] = {u0.x, u0.y, u1.x, u1.y};
#pragma unroll
        for (int si = 0; si < 2; si++)
#pragma unroll
            for (int rj = 0; rj < 4; rj++) {
                a1[si][rj] += av[si]*vv[rj];
                a2[si][rj] += bv[si]*uv[rj];
            }
    }
#pragma unroll
    for (int si = 0; si < 2; si++) {
        int s = sg*2 + si;
#pragma unroll
        for (int rj = 0; rj < 2; rj++) {
            int r = rg*2 + rj;
            float c  = d_cos[s*16 + r];
            float sn = d_sin[s*16 + r];
            float xl = a1[si][rj], xh = a1[si][rj+2];
            float yl = a2[si][rj], yh = a2[si][rj+2];
            int ob = (n*32 + s)*256 + h*32 + r;
            d_g1_c[ob]    = xl*c + xh*sn;
            d_g1_c[ob+16] = xh*c - xl*sn;
            d_g2_c[ob]    = yl*c - yh*sn;
            d_g2_c[ob+16] = yh*c + yl*sn;
        }
    }
}

// ---------------- final: m = g1@u + g2@v, NN GEMM K=512 -------------------
__global__ __launch_bounds__(256) void k_final(const float* __restrict__ U,
                                               const float* __restrict__ V,
                                               float* __restrict__ out, int chan)
{
    __shared__ float As[16][132];
    __shared__ float Bs[16][132];
    const float* G1 = chan ? d_g1_c : d_g1_t;
    const float* G2 = chan ? d_g2_c : d_g2_t;
    int tid = threadIdx.x;
    int m0 = blockIdx.y * 128, n0 = blockIdx.x * 128;
    int tx = tid & 15, ty = tid >> 4;
    float acc[8][8];
#pragma unroll
    for (int i = 0; i < 8; i++)
#pragma unroll
        for (int j = 0; j < 8; j++) acc[i][j] = 0.f;

    for (int k0 = 0; k0 < 512; k0 += 16) {
        const float* Ak = (k0 < 256) ? G1 : G2;
        const float* Wk = (k0 < 256) ? U : V;
        int kk = k0 & 255;
#pragma unroll
        for (int l = 0; l < 2; l++) {
            int lin = tid + l*256;
            int r = lin >> 2, kq = (lin & 3) << 2;
            float4 a = *(const float4*)(Ak + (long long)(m0 + r)*256 + kk + kq);
            As[kq][r] = a.x; As[kq+1][r] = a.y; As[kq+2][r] = a.z; As[kq+3][r] = a.w;
            int k = lin >> 5, j4 = (lin & 31) << 2;
            float4 w = *(const float4*)(Wk + (kk + k)*256 + n0 + j4);
            *(float4*)&Bs[k][j4] = w;
        }
        __syncthreads();
#pragma unroll
        for (int k = 0; k < 16; k++) {
            float a[8], b[8];
            *(float4*)&a[0] = *(const float4*)&As[k][ty*8];
            *(float4*)&a[4] = *(const float4*)&As[k][ty*8+4];
            *(float4*)&b[0] = *(const float4*)&Bs[k][tx*8];
            *(float4*)&b[4] = *(const float4*)&Bs[k][tx*8+4];
#pragma unroll
            for (int i = 0; i < 8; i++)
#pragma unroll
                for (int j = 0; j < 8; j++) acc[i][j] += a[i]*b[j];
        }
        __syncthreads();
    }
#pragma unroll
    for (int i = 0; i < 8; i++) {
        int row = m0 + ty*8 + i;
        int col = n0 + tx*8;
        long long oidx;
        if (!chan) {
            oidx = (long long)row*256 + col;
        } else {
            int nn = row >> 5, c = row & 31;
            int b = nn >> 7, p = nn & 127;
            oidx = (long long)(((b*32 + c)*128 + p))*256 + col;
        }
#pragma unroll
        for (int j4 = 0; j4 < 2; j4++) {
            float4 v;
            v.x = acc[i][j4*4]; v.y = acc[i][j4*4+1];
            v.z = acc[i][j4*4+2]; v.w = acc[i][j4*4+3];
            *reinterpret_cast<float4*>(&out[oidx + j4*4]) = v;
        }
    }
}

// ---------------- launch ---------------------------------------------------
extern "C" void kernel_launch(void* const* d_in, const int* in_sizes, int n_in,
                              void* d_out, int out_size)
{
    const float* qz = (const float*)d_in[0];
    const float* mask_t = (const float*)d_in[1];
    const float* mask_c = (const float*)d_in[2];
    const float* u_t = (const float*)d_in[3];
    const float* v_t = (const float*)d_in[4];
    const float* u_c = (const float*)d_in[5];
    const float* v_c = (const float*)d_in[6];
    float* out = (float*)d_out;

    k_setup<<<8, 256>>>();

    k_proj<<<dim3(4, 256), 256>>>(qz, u_t, v_t, 0);
    k_proj<<<dim3(4, 256), 256>>>(qz, u_c, v_c, 1);

    k_rope<<<32768, 256>>>(0);
    k_rope<<<32768, 256>>>(1);

    k_ft<<<NT*HH, 256>>>(mask_t);
    k_fc<<<NC*HH, 256>>>(mask_c);

    k_softmax<<<32768, 256>>>();

    k_gt<<<NT*HH, 256>>>();
    k_gc<<<NC*HH, 128>>>();

    k_final<<<dim3(2, 256), 256>>>(u_t, v_t, out, 0);
    k_final<<<dim3(2, 256), 256>>>(u_c, v_c, out + OUT_HALF, 1);
}

// round 9
// speedup vs baseline: 1.8249x; 1.8249x over previous
#include <cuda_runtime.h>
#include <cuda_bf16.h>

typedef unsigned int u32;
typedef unsigned long long u64;

// Problem constants
#define BB 8
#define CC 32
#define PP 128
#define DD 256
#define HH 8
#define RR 32
#define NT (BB*CC)
#define NC (BB*PP)
#define ROWS 32768
#define OUT_HALF (BB*CC*PP*DD)

// ---------------- scratch ----------------
__device__ __align__(256) float d_raw_t[ROWS*512];
__device__ __align__(256) float d_raw_c[ROWS*512];
__device__ __align__(256) float d_qur_t[NT*HH*PP*RR];
__device__ __align__(256) float d_quo_t[NT*HH*PP*RR];
__device__ __align__(256) float d_qvr_t[NT*HH*PP*RR];
__device__ __align__(256) float d_qur_c[NC*HH*CC*RR];
__device__ __align__(256) float d_quo_c[NC*HH*CC*RR];
__device__ __align__(256) float d_qvr_c[NC*HH*CC*RR];
__device__ __align__(256) float d_F_t[NT*HH*PP*PP];
__device__ __align__(256) float d_F_c[NC*HH*CC*CC];
__device__ __align__(256) float d_cos[PP*16];
__device__ __align__(256) float d_sin[PP*16];

__device__ __align__(256) __nv_bfloat16 d_qz0[ROWS*256];
__device__ __align__(256) __nv_bfloat16 d_qz1[ROWS*256];
__device__ __align__(256) __nv_bfloat16 d_qz2[ROWS*256];
__device__ __align__(256) __nv_bfloat16 d_wp_t[3][512*256];
__device__ __align__(256) __nv_bfloat16 d_wp_c[3][512*256];
__device__ __align__(256) __nv_bfloat16 d_wf_t[2][256*512];
__device__ __align__(256) __nv_bfloat16 d_wf_c[2][256*512];
__device__ __align__(256) __nv_bfloat16 d_ga0_t[ROWS*512];
__device__ __align__(256) __nv_bfloat16 d_ga1_t[ROWS*512];
__device__ __align__(256) __nv_bfloat16 d_ga0_c[ROWS*512];
__device__ __align__(256) __nv_bfloat16 d_ga1_c[ROWS*512];

// ---------------- HMMA helpers (baseline PTX, valid on sm_103) -------------
__device__ __forceinline__ void ldm_x4(u32* r, u32 addr) {
    asm volatile("ldmatrix.sync.aligned.m8n8.x4.shared.b16 {%0, %1, %2, %3}, [%4];" : "=r"(r[0]), "=r"(r[1]), "=r"(r[2]), "=r"(r[3]) : "r"(addr));
}
__device__ __forceinline__ void mma_bf16(float* d, const u32* a, const u32* b) {
    asm volatile("mma.sync.aligned.m16n8k16.row.col.f32.bf16.bf16.f32 {%0, %1, %2, %3}, {%4, %5, %6, %7}, {%8, %9}, {%0, %1, %2, %3};" : "+f"(d[0]), "+f"(d[1]), "+f"(d[2]), "+f"(d[3]) : "r"(a[0]), "r"(a[1]), "r"(a[2]), "r"(a[3]), "r"(b[0]), "r"(b[1]));
}

#define TSTRIDE 40              // padded row stride in bf16 (80 bytes)
#define TILE_BYTES 10240        // 128 rows * 80 bytes
#define PROJ_SMEM (6*TILE_BYTES)
#define FIN_SMEM  (4*TILE_BYTES)

__device__ __forceinline__ void st_split(__nv_bfloat16* A0, __nv_bfloat16* A1,
                                         long long i, float x) {
    __nv_bfloat16 b0 = __float2bfloat16(x);
    A0[i] = b0;
    A1[i] = __float2bfloat16(x - __bfloat162float(b0));
}

// ---------------- rope table ----------------
__global__ void k_setup() {
    int idx = blockIdx.x * blockDim.x + threadIdx.x;
    if (idx < PP*16) {
        int s = idx >> 4, i = idx & 15;
        double invf = pow(10000.0, -((double)(2*i)) / 32.0);
        double a = (double)s * invf;
        d_cos[idx] = (float)cos(a);
        d_sin[idx] = (float)sin(a);
    }
}

// ---------------- split qz into 3 bf16 components --------------------------
__global__ __launch_bounds__(256) void k_split_qz(const float* __restrict__ qz) {
    int i = (blockIdx.x * 256 + threadIdx.x) * 4;
    float4 x = *reinterpret_cast<const float4*>(qz + i);
    float xs[4];
    xs[0] = x.x; xs[1] = x.y; xs[2] = x.z; xs[3] = x.w;
    __align__(8) __nv_bfloat16 b0[4], b1[4], b2[4];
#pragma unroll
    for (int j = 0; j < 4; j++) {
        b0[j] = __float2bfloat16(xs[j]);
        float r = xs[j] - __bfloat162float(b0[j]);
        b1[j] = __float2bfloat16(r);
        b2[j] = __float2bfloat16(r - __bfloat162float(b1[j]));
    }
    *reinterpret_cast<uint2*>(&d_qz0[i]) = *reinterpret_cast<uint2*>(b0);
    *reinterpret_cast<uint2*>(&d_qz1[i]) = *reinterpret_cast<uint2*>(b1);
    *reinterpret_cast<uint2*>(&d_qz2[i]) = *reinterpret_cast<uint2*>(b2);
}

__global__ __launch_bounds__(256) void k_split_w(const float* __restrict__ U,
                                                 const float* __restrict__ V, int branch) {
    int idx = blockIdx.x * 256 + threadIdx.x;
    int n = idx >> 8, k = idx & 255;
    float x = (n < 256) ? U[n*256 + k] : V[(n-256)*256 + k];
    __nv_bfloat16* w0 = branch ? d_wp_c[0] : d_wp_t[0];
    __nv_bfloat16* w1 = branch ? d_wp_c[1] : d_wp_t[1];
    __nv_bfloat16* w2 = branch ? d_wp_c[2] : d_wp_t[2];
    __nv_bfloat16 b0 = __float2bfloat16(x);
    float r = x - __bfloat162float(b0);
    __nv_bfloat16 b1 = __float2bfloat16(r);
    w0[idx] = b0; w1[idx] = b1;
    w2[idx] = __float2bfloat16(r - __bfloat162float(b1));
}

__global__ __launch_bounds__(256) void k_split_wf(const float* __restrict__ U,
                                                  const float* __restrict__ V, int branch) {
    int idx = blockIdx.x * 256 + threadIdx.x;
    int n = idx >> 9, k = idx & 511;
    float x = (k < 256) ? U[k*256 + n] : V[(k-256)*256 + n];
    __nv_bfloat16* w0 = branch ? d_wf_c[0] : d_wf_t[0];
    __nv_bfloat16* w1 = branch ? d_wf_c[1] : d_wf_t[1];
    __nv_bfloat16 b0 = __float2bfloat16(x);
    w0[idx] = b0;
    w1[idx] = __float2bfloat16(x - __bfloat162float(b0));
}

// ---------------- proj GEMM (HMMA): raw[32768,512] = qz @ [u|v]^T ----------
// 3-way bf16 split, 6 products. Block 128x128, 8 warps (32x64 each), K=256.
__global__ __launch_bounds__(256, 1) void k_proj_mma(int branch) {
    extern __shared__ char smem[];
    const int tid = threadIdx.x;
    const u32 sbase = (u32)__cvta_generic_to_shared(smem);
    const int n0 = blockIdx.x * 128;
    const int m0 = blockIdx.y * 128;
    const int lane = tid & 31, warp = tid >> 5;
    const int wm = warp >> 1, wn = warp & 1;
    const __nv_bfloat16* W0 = branch ? d_wp_c[0] : d_wp_t[0];
    const __nv_bfloat16* W1 = branch ? d_wp_c[1] : d_wp_t[1];
    const __nv_bfloat16* W2 = branch ? d_wp_c[2] : d_wp_t[2];
    float* out = branch ? d_raw_c : d_raw_t;

    float acc[2][8][4];
#pragma unroll
    for (int mt = 0; mt < 2; mt++)
#pragma unroll
        for (int nt = 0; nt < 8; nt++)
#pragma unroll
            for (int e = 0; e < 4; e++) acc[mt][nt][e] = 0.f;

    for (int kc = 0; kc < 8; kc++) {
        if (kc) __syncthreads();
#pragma unroll
        for (int t = 0; t < 6; t++) {           // A tiles: 3 splits
            int li = tid + t * 256;
            int seg = li & 3, row = (li >> 2) & 127, sp = li >> 9;
            const __nv_bfloat16* As = (sp == 0) ? d_qz0 : (sp == 1) ? d_qz1 : d_qz2;
            int grow = m0 + row;
            if (branch) {
                int b = grow >> 12, rem = grow & 4095;
                grow = ((b << 5) + (rem & 31)) * 128 + (rem >> 5);
            }
            uint4 x = *reinterpret_cast<const uint4*>(As + (long long)grow * 256 + kc * 32 + seg * 8);
            *reinterpret_cast<uint4*>(smem + sp * TILE_BYTES + row * 80 + seg * 16) = x;
        }
#pragma unroll
        for (int t = 0; t < 6; t++) {           // W tiles: 3 splits
            int li = tid + t * 256;
            int seg = li & 3, row = (li >> 2) & 127, sp = li >> 9;
            const __nv_bfloat16* Ws = (sp == 0) ? W0 : (sp == 1) ? W1 : W2;
            uint4 x = *reinterpret_cast<const uint4*>(Ws + (long long)(n0 + row) * 256 + kc * 32 + seg * 8);
            *reinterpret_cast<uint4*>(smem + (3 + sp) * TILE_BYTES + row * 80 + seg * 16) = x;
        }
        __syncthreads();
#pragma unroll
        for (int ks = 0; ks < 2; ks++) {
            u32 afr[3][2][4];
#pragma unroll
            for (int sp = 0; sp < 3; sp++)
#pragma unroll
                for (int mt = 0; mt < 2; mt++) {
                    u32 addr = sbase + sp * TILE_BYTES
                             + (wm * 32 + mt * 16 + (lane & 15)) * 80
                             + ks * 32 + (lane >> 4) * 16;
                    ldm_x4(afr[sp][mt], addr);
                }
#pragma unroll
            for (int sb = 0; sb < 3; sb++) {
                u32 bfr[8][2];
#pragma unroll
                for (int g = 0; g < 4; g++) {
                    u32 tr[4];
                    u32 addr = sbase + (3 + sb) * TILE_BYTES
                             + (wn * 64 + g * 16 + (lane & 15)) * 80
                             + ks * 32 + (lane >> 4) * 16;
                    ldm_x4(tr, addr);
                    bfr[2*g][0] = tr[0];   bfr[2*g][1] = tr[2];
                    bfr[2*g+1][0] = tr[1]; bfr[2*g+1][1] = tr[3];
                }
                int na = 3 - sb;   // sb=0: sa 0..2, sb=1: sa 0..1, sb=2: sa 0
#pragma unroll
                for (int sa = 0; sa < 3; sa++) {
                    if (sa < na) {
#pragma unroll
                        for (int mt = 0; mt < 2; mt++)
#pragma unroll
                            for (int nt = 0; nt < 8; nt++)
                                mma_bf16(acc[mt][nt], afr[sa][mt], bfr[nt]);
                    }
                }
            }
        }
    }
#pragma unroll
    for (int mt = 0; mt < 2; mt++)
#pragma unroll
        for (int nt = 0; nt < 8; nt++) {
            int r = m0 + wm * 32 + mt * 16 + (lane >> 2);
            int c = n0 + wn * 64 + nt * 8 + (lane & 3) * 2;
            float2 lo; lo.x = acc[mt][nt][0]; lo.y = acc[mt][nt][1];
            float2 hi; hi.x = acc[mt][nt][2]; hi.y = acc[mt][nt][3];
            *reinterpret_cast<float2*>(&out[(long long)r * 512 + c]) = lo;
            *reinterpret_cast<float2*>(&out[(long long)(r + 8) * 512 + c]) = hi;
        }
}

// ---------------- final GEMM (HMMA): out[32768,256] = [g1|g2] @ wf^T -------
// 2-way bf16 split, 3 products. K=512.
__global__ __launch_bounds__(256, 1) void k_final_mma(float* __restrict__ out, int branch) {
    extern __shared__ char smem[];
    const int tid = threadIdx.x;
    const u32 sbase = (u32)__cvta_generic_to_shared(smem);
    const int n0 = blockIdx.x * 128;
    const int m0 = blockIdx.y * 128;
    const int lane = tid & 31, warp = tid >> 5;
    const int wm = warp >> 1, wn = warp & 1;
    const __nv_bfloat16* G0 = branch ? d_ga0_c : d_ga0_t;
    const __nv_bfloat16* G1 = branch ? d_ga1_c : d_ga1_t;
    const __nv_bfloat16* F0 = branch ? d_wf_c[0] : d_wf_t[0];
    const __nv_bfloat16* F1 = branch ? d_wf_c[1] : d_wf_t[1];

    float acc[2][8][4];
#pragma unroll
    for (int mt = 0; mt < 2; mt++)
#pragma unroll
        for (int nt = 0; nt < 8; nt++)
#pragma unroll
            for (int e = 0; e < 4; e++) acc[mt][nt][e] = 0.f;

    for (int kc = 0; kc < 16; kc++) {
        if (kc) __syncthreads();
#pragma unroll
        for (int t = 0; t < 4; t++) {           // A tiles: 2 splits
            int li = tid + t * 256;
            int seg = li & 3, row = (li >> 2) & 127, sp = li >> 9;
            const __nv_bfloat16* As = (sp == 0) ? G0 : G1;
            uint4 x = *reinterpret_cast<const uint4*>(As + (long long)(m0 + row) * 512 + kc * 32 + seg * 8);
            *reinterpret_cast<uint4*>(smem + sp * TILE_BYTES + row * 80 + seg * 16) = x;
        }
#pragma unroll
        for (int t = 0; t < 4; t++) {           // W tiles: 2 splits
            int li = tid + t * 256;
            int seg = li & 3, row = (li >> 2) & 127, sp = li >> 9;
            const __nv_bfloat16* Ws = (sp == 0) ? F0 : F1;
            uint4 x = *reinterpret_cast<const uint4*>(Ws + (long long)(n0 + row) * 512 + kc * 32 + seg * 8);
            *reinterpret_cast<uint4*>(smem + (2 + sp) * TILE_BYTES + row * 80 + seg * 16) = x;
        }
        __syncthreads();
#pragma unroll
        for (int ks = 0; ks < 2; ks++) {
            u32 afr[2][2][4];
#pragma unroll
            for (int sp = 0; sp < 2; sp++)
#pragma unroll
                for (int mt = 0; mt < 2; mt++) {
                    u32 addr = sbase + sp * TILE_BYTES
                             + (wm * 32 + mt * 16 + (lane & 15)) * 80
                             + ks * 32 + (lane >> 4) * 16;
                    ldm_x4(afr[sp][mt], addr);
                }
#pragma unroll
            for (int sb = 0; sb < 2; sb++) {
                u32 bfr[8][2];
#pragma unroll
                for (int g = 0; g < 4; g++) {
                    u32 tr[4];
                    u32 addr = sbase + (2 + sb) * TILE_BYTES
                             + (wn * 64 + g * 16 + (lane & 15)) * 80
                             + ks * 32 + (lane >> 4) * 16;
                    ldm_x4(tr, addr);
                    bfr[2*g][0] = tr[0];   bfr[2*g][1] = tr[2];
                    bfr[2*g+1][0] = tr[1]; bfr[2*g+1][1] = tr[3];
                }
                int na = 2 - sb;   // sb=0: sa 0..1, sb=1: sa 0
#pragma unroll
                for (int sa = 0; sa < 2; sa++) {
                    if (sa < na) {
#pragma unroll
                        for (int mt = 0; mt < 2; mt++)
#pragma unroll
                            for (int nt = 0; nt < 8; nt++)
                                mma_bf16(acc[mt][nt], afr[sa][mt], bfr[nt]);
                    }
                }
            }
        }
    }
#pragma unroll
    for (int mt = 0; mt < 2; mt++)
#pragma unroll
        for (int nt = 0; nt < 8; nt++) {
            int r = m0 + wm * 32 + mt * 16 + (lane >> 2);
            int c = n0 + wn * 64 + nt * 8 + (lane & 3) * 2;
            long long r0o, r1o;
            if (!branch) {
                r0o = (long long)r; r1o = (long long)(r + 8);
            } else {
                int nn = r >> 5, cc2 = r & 31;
                int b = nn >> 7, p = nn & 127;
                r0o = (long long)((b * 32 + cc2) * 128 + p);
                int r8 = r + 8;
                nn = r8 >> 5; cc2 = r8 & 31; b = nn >> 7; p = nn & 127;
                r1o = (long long)((b * 32 + cc2) * 128 + p);
            }
            float2 lo; lo.x = acc[mt][nt][0]; lo.y = acc[mt][nt][1];
            float2 hi; hi.x = acc[mt][nt][2]; hi.y = acc[mt][nt][3];
            *reinterpret_cast<float2*>(&out[r0o * 256 + c]) = lo;
            *reinterpret_cast<float2*>(&out[r1o * 256 + c]) = hi;
        }
}

// ---------------- RoPE ------------------------------------------------------
__global__ __launch_bounds__(256) void k_rope(int branch) {
    const float* raw = branch ? d_raw_c : d_raw_t;
    float* qur = branch ? d_qur_c : d_qur_t;
    float* quo = branch ? d_quo_c : d_quo_t;
    float* qvr = branch ? d_qvr_c : d_qvr_t;
    int Sbits = branch ? 5 : 7;

    int warp = threadIdx.x >> 5, lane = threadIdx.x & 31;
    int task = blockIdx.x * 8 + warp;
    int h = task & 7;
    int row = task >> 3;
    int S = 1 << Sbits;
    int s = row & (S - 1);
    int n = row >> Sbits;

    float qu = raw[(long long)row*512 + h*32 + lane];
    float qv = raw[(long long)row*512 + 256 + h*32 + lane];
    float c  = d_cos[s*16 + (lane & 15)];
    float sn = d_sin[s*16 + (lane & 15)];
    float pu = __shfl_xor_sync(0xffffffffu, qu, 16);
    float pv = __shfl_xor_sync(0xffffffffu, qv, 16);
    float sgn = (lane < 16) ? -1.f : 1.f;
    int ob = ((n*8 + h)*S + s)*32 + lane;
    qur[ob] = qu*c + sgn*pu*sn;
    quo[ob] = qu*c - sgn*pu*sn;
    qvr[ob] = qv*c + sgn*pv*sn;
}

// ---------------- F_t -------------------------------------------------------
__global__ __launch_bounds__(256) void k_ft(const float* __restrict__ mask) {
    __shared__ float SuT[32][132];
    __shared__ float SvT[32][132];
    int nh = blockIdx.x;
    int n = nh >> 3;
    const float* ubase = d_qur_t + nh*128*32;
    const float* vbase = d_qvr_t + nh*128*32;
    int tid = threadIdx.x;
#pragma unroll
    for (int l = 0; l < 4; l++) {
        int lin = tid + l*256;
        int s = lin >> 3, rq = (lin & 7) << 2;
        float4 u = *reinterpret_cast<const float4*>(ubase + s*32 + rq);
        SuT[rq][s] = u.x; SuT[rq+1][s] = u.y; SuT[rq+2][s] = u.z; SuT[rq+3][s] = u.w;
        float4 v = *reinterpret_cast<const float4*>(vbase + s*32 + rq);
        SvT[rq][s] = v.x; SvT[rq+1][s] = v.y; SvT[rq+2][s] = v.z; SvT[rq+3][s] = v.w;
    }
    __syncthreads();
    int tx = tid & 15, ty = tid >> 4;
    float acc[8][8];
#pragma unroll
    for (int i = 0; i < 8; i++)
#pragma unroll
        for (int j = 0; j < 8; j++) acc[i][j] = 0.f;
#pragma unroll
    for (int k = 0; k < 32; k++) {
        float a[8], b[8];
        *(float4*)&a[0] = *(const float4*)&SuT[k][ty*8];
        *(float4*)&a[4] = *(const float4*)&SuT[k][ty*8+4];
        *(float4*)&b[0] = *(const float4*)&SvT[k][tx*8];
        *(float4*)&b[4] = *(const float4*)&SvT[k][tx*8+4];
#pragma unroll
        for (int i = 0; i < 8; i++)
#pragma unroll
            for (int j = 0; j < 8; j++) acc[i][j] += a[i]*b[j];
    }
    float* fout = d_F_t + (long long)nh*16384;
    const float* mrow = mask + (long long)n*16384;
#pragma unroll
    for (int i = 0; i < 8; i++) {
        int s = ty*8 + i;
#pragma unroll
        for (int j4 = 0; j4 < 2; j4++) {
            int t = tx*8 + j4*4;
            float4 m4 = *reinterpret_cast<const float4*>(mrow + s*128 + t);
            float4 o;
            o.x = acc[i][j4*4]   + m4.x;
            o.y = acc[i][j4*4+1] + m4.y;
            o.z = acc[i][j4*4+2] + m4.z;
            o.w = acc[i][j4*4+3] + m4.w;
            *reinterpret_cast<float4*>(fout + s*128 + t) = o;
        }
    }
}

// ---------------- F_c -------------------------------------------------------
__global__ __launch_bounds__(256) void k_fc(const float* __restrict__ mask) {
    __shared__ float SuT[32][36];
    __shared__ float SvT[32][36];
    int nh = blockIdx.x;
    int n = nh >> 3;
    const float* ubase = d_qur_c + nh*1024;
    const float* vbase = d_qvr_c + nh*1024;
    int tid = threadIdx.x;
    {
        int s = tid >> 3, rq = (tid & 7) << 2;
        float4 u = *reinterpret_cast<const float4*>(ubase + s*32 + rq);
        SuT[rq][s] = u.x; SuT[rq+1][s] = u.y; SuT[rq+2][s] = u.z; SuT[rq+3][s] = u.w;
        float4 v = *reinterpret_cast<const float4*>(vbase + s*32 + rq);
        SvT[rq][s] = v.x; SvT[rq+1][s] = v.y; SvT[rq+2][s] = v.z; SvT[rq+3][s] = v.w;
    }
    __syncthreads();
    int tx = tid & 7, ty = tid >> 3;
    float acc[4];
    acc[0] = 0.f; acc[1] = 0.f; acc[2] = 0.f; acc[3] = 0.f;
#pragma unroll
    for (int k = 0; k < 32; k++) {
        float a = SuT[k][ty];
        float4 b = *(const float4*)&SvT[k][tx*4];
        acc[0] += a*b.x; acc[1] += a*b.y; acc[2] += a*b.z; acc[3] += a*b.w;
    }
    int t0 = tx*4;
    float4 m4 = *reinterpret_cast<const float4*>(mask + (long long)n*1024 + ty*32 + t0);
    float4 o;
    o.x = acc[0] + m4.x; o.y = acc[1] + m4.y; o.z = acc[2] + m4.z; o.w = acc[3] + m4.w;
    *reinterpret_cast<float4*>(d_F_c + (long long)nh*1024 + ty*32 + t0) = o;
}

// ---------------- joint softmax --------------------------------------------
__global__ __launch_bounds__(256) void k_softmax() {
    int warp = threadIdx.x >> 5, lane = threadIdx.x & 31;
    int rowid = blockIdx.x * 8 + warp;
    int p  = rowid & 127;
    int r1 = rowid >> 7;
    int c  = r1 & 31;
    int r2 = r1 >> 5;
    int h  = r2 & 7;
    int b  = r2 >> 3;
    float* ft = d_F_t + ((long long)(((b*32 + c)*8 + h)*128 + p))*128;
    float* fc = d_F_c + ((long long)(((b*128 + p)*8 + h)*32 + c))*32;
    float v[5];
    v[0] = ft[lane]; v[1] = ft[lane+32]; v[2] = ft[lane+64]; v[3] = ft[lane+96];
    v[4] = fc[lane];
    float m = v[0];
#pragma unroll
    for (int i = 1; i < 5; i++) m = fmaxf(m, v[i]);
#pragma unroll
    for (int off = 16; off >= 1; off >>= 1)
        m = fmaxf(m, __shfl_xor_sync(0xffffffffu, m, off));
    float sum = 0.f;
#pragma unroll
    for (int i = 0; i < 5; i++) { v[i] = expf(256.f*(v[i] - m)); sum += v[i]; }
#pragma unroll
    for (int off = 16; off >= 1; off >>= 1)
        sum += __shfl_xor_sync(0xffffffffu, sum, off);
    float inv = 1.f / sum;
    ft[lane]     = v[0]*inv;
    ft[lane+32]  = v[1]*inv;
    ft[lane+64]  = v[2]*inv;
    ft[lane+96]  = v[3]*inv;
    fc[lane]     = v[4]*inv;
}

// ---------------- G time ----------------------------------------------------
__global__ __launch_bounds__(256) void k_gt() {
    __shared__ float Qa[32][132];
    __shared__ float Qb[32][132];
    __shared__ float Vs[32][34];
    __shared__ float Us[32][34];
    int nh = blockIdx.x;
    int n = nh >> 3, h = nh & 7;
    const float* qh = d_F_t + (long long)nh*16384;
    const float* vb = d_qvr_t + nh*4096;
    const float* ub = d_quo_t + nh*4096;
    int tid = threadIdx.x;
    int rg = tid & 7, sg = tid >> 3;
    float a1[4][4], a2[4][4];
#pragma unroll
    for (int i = 0; i < 4; i++)
#pragma unroll
        for (int j = 0; j < 4; j++) { a1[i][j] = 0.f; a2[i][j] = 0.f; }

    for (int t0 = 0; t0 < 128; t0 += 32) {
        __syncthreads();
#pragma unroll
        for (int l = 0; l < 4; l++) {
            int lin = tid + l*256;
            int s = lin >> 3, iq = (lin & 7) << 2;
            float4 q = *(const float4*)(qh + s*128 + t0 + iq);
            Qa[iq][s] = q.x; Qa[iq+1][s] = q.y; Qa[iq+2][s] = q.z; Qa[iq+3][s] = q.w;
        }
#pragma unroll
        for (int l = 0; l < 4; l++) {
            int lin = tid + l*256;
            int i = lin >> 5, sq = (lin & 31) << 2;
            float4 q = *(const float4*)(qh + (t0 + i)*128 + sq);
            *(float4*)&Qb[i][sq] = q;
        }
        {
            int i = tid >> 3, rq = (tid & 7) << 2;
            float4 v = *(const float4*)(vb + (t0 + i)*32 + rq);
            Vs[i][rq] = v.x; Vs[i][rq+1] = v.y; Vs[i][rq+2] = v.z; Vs[i][rq+3] = v.w;
            float4 u = *(const float4*)(ub + (t0 + i)*32 + rq);
            Us[i][rq] = u.x; Us[i][rq+1] = u.y; Us[i][rq+2] = u.z; Us[i][rq+3] = u.w;
        }
        __syncthreads();
#pragma unroll
        for (int i = 0; i < 32; i++) {
            float4 qa = *(const float4*)&Qa[i][sg*4];
            float4 qb = *(const float4*)&Qb[i][sg*4];
            float2 v0 = *(const float2*)&Vs[i][rg*2];
            float2 v1 = *(const float2*)&Vs[i][rg*2+16];
            float2 u0 = *(const float2*)&Us[i][rg*2];
            float2 u1 = *(const float2*)&Us[i][rg*2+16];
            float av[4], bv[4], vv[4], uv[4];
            av[0] = qa.x; av[1] = qa.y; av[2] = qa.z; av[3] = qa.w;
            bv[0] = qb.x; bv[1] = qb.y; bv[2] = qb.z; bv[3] = qb.w;
            vv[0] = v0.x; vv[1] = v0.y; vv[2] = v1.x; vv[3] = v1.y;
            uv[0] = u0.x; uv[1] = u0.y; uv[2] = u1.x; uv[3] = u1.y;
#pragma unroll
            for (int si = 0; si < 4; si++)
#pragma unroll
                for (int rj = 0; rj < 4; rj++) {
                    a1[si][rj] += av[si]*vv[rj];
                    a2[si][rj] += bv[si]*uv[rj];
                }
        }
    }
#pragma unroll
    for (int si = 0; si < 4; si++) {
        int s = sg*4 + si;
        long long rb = (long long)(n*128 + s) * 512;
#pragma unroll
        for (int rj = 0; rj < 2; rj++) {
            int r = rg*2 + rj;
            float c  = d_cos[s*16 + r];
            float sn = d_sin[s*16 + r];
            float xl = a1[si][rj], xh = a1[si][rj+2];
            float yl = a2[si][rj], yh = a2[si][rj+2];
            int col = h*32 + r;
            st_split(d_ga0_t, d_ga1_t, rb + col,        xl*c + xh*sn);
            st_split(d_ga0_t, d_ga1_t, rb + col + 16,   xh*c - xl*sn);
            st_split(d_ga0_t, d_ga1_t, rb + 256 + col,      yl*c - yh*sn);
            st_split(d_ga0_t, d_ga1_t, rb + 256 + col + 16, yh*c + yl*sn);
        }
    }
}

// ---------------- G chan ----------------------------------------------------
__global__ __launch_bounds__(128) void k_gc() {
    __shared__ float Qn[32][34];
    __shared__ float Vs[32][34];
    __shared__ float Us[32][34];
    int nh = blockIdx.x;
    int n = nh >> 3, h = nh & 7;
    const float* qh = d_F_c + (long long)nh*1024;
    const float* vb = d_qvr_c + nh*1024;
    const float* ub = d_quo_c + nh*1024;
    int tid = threadIdx.x;
#pragma unroll
    for (int l = 0; l < 2; l++) {
        int lin = tid + l*128;
        int t = lin >> 3, sq = (lin & 7) << 2;
        float4 q = *(const float4*)(qh + t*32 + sq);
        Qn[t][sq] = q.x; Qn[t][sq+1] = q.y; Qn[t][sq+2] = q.z; Qn[t][sq+3] = q.w;
        float4 v = *(const float4*)(vb + t*32 + sq);
        Vs[t][sq] = v.x; Vs[t][sq+1] = v.y; Vs[t][sq+2] = v.z; Vs[t][sq+3] = v.w;
        float4 u = *(const float4*)(ub + t*32 + sq);
        Us[t][sq] = u.x; Us[t][sq+1] = u.y; Us[t][sq+2] = u.z; Us[t][sq+3] = u.w;
    }
    __syncthreads();
    int rg = tid & 7, sg = tid >> 3;
    float a1[2][4], a2[2][4];
#pragma unroll
    for (int i = 0; i < 2; i++)
#pragma unroll
        for (int j = 0; j < 4; j++) { a1[i][j] = 0.f; a2[i][j] = 0.f; }
#pragma unroll
    for (int t = 0; t < 32; t++) {
        float av[2], bv[2], vv[4], uv[4];
        av[0] = Qn[sg*2][t];
        av[1] = Qn[sg*2+1][t];
        float2 qb = *(const float2*)&Qn[t][sg*2];
        float2 v0 = *(const float2*)&Vs[t][rg*2];
        float2 v1 = *(const float2*)&Vs[t][rg*2+16];
        float2 u0 = *(const float2*)&Us[t][rg*2];
        float2 u1 = *(const float2*)&Us[t][rg*2+16];
        bv[0] = qb.x; bv[1] = qb.y;
        vv[0] = v0.x; vv[1] = v0.y; vv[2] = v1.x; vv[3] = v1.y;
        uv[0] = u0.x; uv[1] = u0.y; uv[2] = u1.x; uv[3] = u1.y;
#pragma unroll
        for (int si = 0; si < 2; si++)
#pragma unroll
            for (int rj = 0; rj < 4; rj++) {
                a1[si][rj] += av[si]*vv[rj];
                a2[si][rj] += bv[si]*uv[rj];
            }
    }
#pragma unroll
    for (int si = 0; si < 2; si++) {
        int s = sg*2 + si;
        long long rb = (long long)(n*32 + s) * 512;
#pragma unroll
        for (int rj = 0; rj < 2; rj++) {
            int r = rg*2 + rj;
            float c  = d_cos[s*16 + r];
            float sn = d_sin[s*16 + r];
            float xl = a1[si][rj], xh = a1[si][rj+2];
            float yl = a2[si][rj], yh = a2[si][rj+2];
            int col = h*32 + r;
            st_split(d_ga0_c, d_ga1_c, rb + col,        xl*c + xh*sn);
            st_split(d_ga0_c, d_ga1_c, rb + col + 16,   xh*c - xl*sn);
            st_split(d_ga0_c, d_ga1_c, rb + 256 + col,      yl*c - yh*sn);
            st_split(d_ga0_c, d_ga1_c, rb + 256 + col + 16, yh*c + yl*sn);
        }
    }
}

// ---------------- launch ---------------------------------------------------
extern "C" void kernel_launch(void* const* d_in, const int* in_sizes, int n_in,
                              void* d_out, int out_size)
{
    const float* qz = (const float*)d_in[0];
    const float* mask_t = (const float*)d_in[1];
    const float* mask_c = (const float*)d_in[2];
    const float* u_t = (const float*)d_in[3];
    const float* v_t = (const float*)d_in[4];
    const float* u_c = (const float*)d_in[5];
    const float* v_c = (const float*)d_in[6];
    float* out = (float*)d_out;

    cudaFuncSetAttribute(k_proj_mma, cudaFuncAttributeMaxDynamicSharedMemorySize, PROJ_SMEM);
    cudaFuncSetAttribute(k_final_mma, cudaFuncAttributeMaxDynamicSharedMemorySize, FIN_SMEM);

    k_setup<<<8, 256>>>();
    k_split_qz<<<8192, 256>>>(qz);
    k_split_w<<<512, 256>>>(u_t, v_t, 0);
    k_split_w<<<512, 256>>>(u_c, v_c, 1);
    k_split_wf<<<512, 256>>>(u_t, v_t, 0);
    k_split_wf<<<512, 256>>>(u_c, v_c, 1);

    k_proj_mma<<<dim3(4, 256), 256, PROJ_SMEM>>>(0);
    k_proj_mma<<<dim3(4, 256), 256, PROJ_SMEM>>>(1);

    k_rope<<<32768, 256>>>(0);
    k_rope<<<32768, 256>>>(1);

    k_ft<<<NT*HH, 256>>>(mask_t);
    k_fc<<<NC*HH, 256>>>(mask_c);

    k_softmax<<<32768, 256>>>();

    k_gt<<<NT*HH, 256>>>();
    k_gc<<<NC*HH, 128>>>();

    k_final_mma<<<dim3(2, 256), 256, FIN_SMEM>>>(out, 0);
    k_final_mma<<<dim3(2, 256), 256, FIN_SMEM>>>(out + OUT_HALF, 1);
}

// round 10
// speedup vs baseline: 2.2091x; 1.2106x over previous
#include <cuda_runtime.h>
#include <cuda_bf16.h>

typedef unsigned int u32;
typedef unsigned long long u64;

// Problem constants
#define BB 8
#define CC 32
#define PP 128
#define DD 256
#define HH 8
#define RR 32
#define NT (BB*CC)
#define NC (BB*PP)
#define ROWS 32768
#define OUT_HALF (BB*CC*PP*DD)

// ---------------- scratch ----------------
__device__ __align__(256) float d_qur_t[NT*HH*PP*RR];
__device__ __align__(256) float d_quo_t[NT*HH*PP*RR];
__device__ __align__(256) float d_qvr_t[NT*HH*PP*RR];
__device__ __align__(256) float d_qur_c[NC*HH*CC*RR];
__device__ __align__(256) float d_quo_c[NC*HH*CC*RR];
__device__ __align__(256) float d_qvr_c[NC*HH*CC*RR];
__device__ __align__(256) float d_F_t[NT*HH*PP*PP];
__device__ __align__(256) float d_F_c[NC*HH*CC*CC];
__device__ __align__(256) float d_cos[PP*16];
__device__ __align__(256) float d_sin[PP*16];

__device__ __align__(256) __nv_bfloat16 d_qz0[ROWS*256];
__device__ __align__(256) __nv_bfloat16 d_qz1[ROWS*256];
__device__ __align__(256) __nv_bfloat16 d_qz2[ROWS*256];
__device__ __align__(256) __nv_bfloat16 d_wp_t[3][512*256];
__device__ __align__(256) __nv_bfloat16 d_wp_c[3][512*256];
__device__ __align__(256) __nv_bfloat16 d_wf_t[2][256*512];
__device__ __align__(256) __nv_bfloat16 d_wf_c[2][256*512];
__device__ __align__(256) __nv_bfloat16 d_ga0_t[ROWS*512];
__device__ __align__(256) __nv_bfloat16 d_ga1_t[ROWS*512];
__device__ __align__(256) __nv_bfloat16 d_ga0_c[ROWS*512];
__device__ __align__(256) __nv_bfloat16 d_ga1_c[ROWS*512];

// ---------------- HMMA + cp.async helpers (baseline PTX) -------------------
__device__ __forceinline__ void ldm_x4(u32* r, u32 addr) {
    asm volatile("ldmatrix.sync.aligned.m8n8.x4.shared.b16 {%0, %1, %2, %3}, [%4];" : "=r"(r[0]), "=r"(r[1]), "=r"(r[2]), "=r"(r[3]) : "r"(addr));
}
__device__ __forceinline__ void mma_bf16(float* d, const u32* a, const u32* b) {
    asm volatile("mma.sync.aligned.m16n8k16.row.col.f32.bf16.bf16.f32 {%0, %1, %2, %3}, {%4, %5, %6, %7}, {%8, %9}, {%0, %1, %2, %3};" : "+f"(d[0]), "+f"(d[1]), "+f"(d[2]), "+f"(d[3]) : "r"(a[0]), "r"(a[1]), "r"(a[2]), "r"(a[3]), "r"(b[0]), "r"(b[1]));
}
__device__ __forceinline__ void cpa(u32 s, const __nv_bfloat16* g) {
    asm volatile("cp.async.ca.shared.global [%0], [%1], 16;" :: "r"(s), "l"((u64)__cvta_generic_to_global((void*)g)) : "memory");
}
__device__ __forceinline__ void cpa_commit() { asm volatile("cp.async.commit_group;" ::: "memory"); }
__device__ __forceinline__ void cpa_wait0() { asm volatile("cp.async.wait_group 0;" ::: "memory"); }
__device__ __forceinline__ void cpa_wait1() { asm volatile("cp.async.wait_group 1;" ::: "memory"); }

#define TILE_BYTES 10240        // 128 rows * 80 bytes
#define PROJ_SMEM (2*6*TILE_BYTES)
#define FIN_SMEM  (2*4*TILE_BYTES)

__device__ __forceinline__ void st_split(__nv_bfloat16* A0, __nv_bfloat16* A1,
                                         long long i, float x) {
    __nv_bfloat16 b0 = __float2bfloat16(x);
    A0[i] = b0;
    A1[i] = __float2bfloat16(x - __bfloat162float(b0));
}

// ---------------- rope table ----------------
__global__ void k_setup() {
    int idx = blockIdx.x * blockDim.x + threadIdx.x;
    if (idx < PP*16) {
        int s = idx >> 4, i = idx & 15;
        double invf = pow(10000.0, -((double)(2*i)) / 32.0);
        double a = (double)s * invf;
        d_cos[idx] = (float)cos(a);
        d_sin[idx] = (float)sin(a);
    }
}

// ---------------- split qz into 3 bf16 components --------------------------
__global__ __launch_bounds__(256) void k_split_qz(const float* __restrict__ qz) {
    int i = (blockIdx.x * 256 + threadIdx.x) * 4;
    float4 x = *reinterpret_cast<const float4*>(qz + i);
    float xs[4];
    xs[0] = x.x; xs[1] = x.y; xs[2] = x.z; xs[3] = x.w;
    __align__(8) __nv_bfloat16 b0[4], b1[4], b2[4];
#pragma unroll
    for (int j = 0; j < 4; j++) {
        b0[j] = __float2bfloat16(xs[j]);
        float r = xs[j] - __bfloat162float(b0[j]);
        b1[j] = __float2bfloat16(r);
        b2[j] = __float2bfloat16(r - __bfloat162float(b1[j]));
    }
    *reinterpret_cast<uint2*>(&d_qz0[i]) = *reinterpret_cast<uint2*>(b0);
    *reinterpret_cast<uint2*>(&d_qz1[i]) = *reinterpret_cast<uint2*>(b1);
    *reinterpret_cast<uint2*>(&d_qz2[i]) = *reinterpret_cast<uint2*>(b2);
}

__global__ __launch_bounds__(256) void k_split_w(const float* __restrict__ U,
                                                 const float* __restrict__ V, int branch) {
    int idx = blockIdx.x * 256 + threadIdx.x;
    int n = idx >> 8, k = idx & 255;
    float x = (n < 256) ? U[n*256 + k] : V[(n-256)*256 + k];
    __nv_bfloat16* w0 = branch ? d_wp_c[0] : d_wp_t[0];
    __nv_bfloat16* w1 = branch ? d_wp_c[1] : d_wp_t[1];
    __nv_bfloat16* w2 = branch ? d_wp_c[2] : d_wp_t[2];
    __nv_bfloat16 b0 = __float2bfloat16(x);
    float r = x - __bfloat162float(b0);
    __nv_bfloat16 b1 = __float2bfloat16(r);
    w0[idx] = b0; w1[idx] = b1;
    w2[idx] = __float2bfloat16(r - __bfloat162float(b1));
}

__global__ __launch_bounds__(256) void k_split_wf(const float* __restrict__ U,
                                                  const float* __restrict__ V, int branch) {
    int idx = blockIdx.x * 256 + threadIdx.x;
    int n = idx >> 9, k = idx & 511;
    float x = (k < 256) ? U[k*256 + n] : V[(k-256)*256 + n];
    __nv_bfloat16* w0 = branch ? d_wf_c[0] : d_wf_t[0];
    __nv_bfloat16* w1 = branch ? d_wf_c[1] : d_wf_t[1];
    __nv_bfloat16 b0 = __float2bfloat16(x);
    w0[idx] = b0;
    w1[idx] = __float2bfloat16(x - __bfloat162float(b0));
}

// ---------------- proj GEMM (HMMA, cp.async pipeline, fused RoPE) ----------
// qz @ [u|v]^T -> RoPE -> qur/quo/qvr directly. 3-way split, 6 products.
__global__ __launch_bounds__(256, 1) void k_proj_mma(int branch) {
    extern __shared__ char smem[];
    const int tid = threadIdx.x;
    const u32 sbase = (u32)__cvta_generic_to_shared(smem);
    const int n0 = blockIdx.x * 128;
    const int m0 = blockIdx.y * 128;
    const int lane = tid & 31, warp = tid >> 5;
    const int wm = warp >> 1, wn = warp & 1;
    const __nv_bfloat16* W0 = branch ? d_wp_c[0] : d_wp_t[0];
    const __nv_bfloat16* W1 = branch ? d_wp_c[1] : d_wp_t[1];
    const __nv_bfloat16* W2 = branch ? d_wp_c[2] : d_wp_t[2];

    float acc[2][8][4];
#pragma unroll
    for (int mt = 0; mt < 2; mt++)
#pragma unroll
        for (int nt = 0; nt < 8; nt++)
#pragma unroll
            for (int e = 0; e < 4; e++) acc[mt][nt][e] = 0.f;

    // stage loader via cp.async: 12 segs/thread (6 tiles x 128 rows x 4 segs)
#pragma unroll 1
    for (int kc = -1; kc < 8; kc++) {
        int ld = kc + 1;
        if (ld < 8) {
            u32 stb = sbase + (u32)(ld & 1) * (6*TILE_BYTES);
#pragma unroll
            for (int t = 0; t < 12; t++) {
                int li = tid + t * 256;
                int seg = li & 3, row = (li >> 2) & 127, tile = li >> 9;
                const __nv_bfloat16* src;
                if (tile < 3) {
                    int grow = m0 + row;
                    if (branch) {
                        int b = grow >> 12, rem = grow & 4095;
                        grow = ((b << 5) + (rem & 31)) * 128 + (rem >> 5);
                    }
                    const __nv_bfloat16* A = (tile == 0) ? d_qz0 : (tile == 1) ? d_qz1 : d_qz2;
                    src = A + (long long)grow * 256 + ld * 32 + seg * 8;
                } else {
                    const __nv_bfloat16* W = (tile == 3) ? W0 : (tile == 4) ? W1 : W2;
                    src = W + (long long)(n0 + row) * 256 + ld * 32 + seg * 8;
                }
                cpa(stb + (u32)(tile * TILE_BYTES + row * 80 + seg * 16), src);
            }
            cpa_commit();
        }
        if (kc < 0) continue;
        if (kc < 7) cpa_wait1(); else cpa_wait0();
        __syncthreads();
        u32 stb = sbase + (u32)(kc & 1) * (6*TILE_BYTES);
#pragma unroll
        for (int ks = 0; ks < 2; ks++) {
            u32 afr[3][2][4];
#pragma unroll
            for (int sp = 0; sp < 3; sp++)
#pragma unroll
                for (int mt = 0; mt < 2; mt++) {
                    u32 addr = stb + sp * TILE_BYTES
                             + (wm * 32 + mt * 16 + (lane & 15)) * 80
                             + ks * 32 + (lane >> 4) * 16;
                    ldm_x4(afr[sp][mt], addr);
                }
#pragma unroll
            for (int sb = 0; sb < 3; sb++) {
                u32 bfr[8][2];
#pragma unroll
                for (int g = 0; g < 4; g++) {
                    u32 tr[4];
                    u32 addr = stb + (3 + sb) * TILE_BYTES
                             + (wn * 64 + g * 16 + (lane & 15)) * 80
                             + ks * 32 + (lane >> 4) * 16;
                    ldm_x4(tr, addr);
                    bfr[2*g][0] = tr[0];   bfr[2*g][1] = tr[2];
                    bfr[2*g+1][0] = tr[1]; bfr[2*g+1][1] = tr[3];
                }
                int na = 3 - sb;
#pragma unroll
                for (int sa = 0; sa < 3; sa++) {
                    if (sa < na) {
#pragma unroll
                        for (int mt = 0; mt < 2; mt++)
#pragma unroll
                            for (int nt = 0; nt < 8; nt++)
                                mma_bf16(acc[mt][nt], afr[sa][mt], bfr[nt]);
                    }
                }
            }
        }
        __syncthreads();
    }

    // ------- fused RoPE epilogue: partner col (xor 16) = acc[mt][nt^2] -----
    float* OUR = branch ? d_qur_c : d_qur_t;
    float* OUO = branch ? d_quo_c : d_quo_t;
    float* OVR = branch ? d_qvr_c : d_qvr_t;
    const int Sbits = branch ? 5 : 7;
    const int Smask = (1 << Sbits) - 1;
    const int isQV = (n0 >= 256);
#pragma unroll
    for (int mt = 0; mt < 2; mt++) {
        int rA = m0 + wm * 32 + mt * 16 + (lane >> 2);
        int rB = rA + 8;
        int nA = rA >> Sbits, sA = rA & Smask;
        int nB = rB >> Sbits, sB = rB & Smask;
#pragma unroll
        for (int nt = 0; nt < 8; nt++) {
            int colh = (n0 & 255) + wn * 64 + nt * 8;
            int rr = (colh & 31) + (lane & 3) * 2;
            int h = (colh >> 5) & 7;
            float sgn = (rr < 16) ? -1.f : 1.f;
            int ci = rr & 15;
            float cA0 = d_cos[sA*16 + ci],     snA0 = d_sin[sA*16 + ci];
            float cA1 = d_cos[sA*16 + ci + 1], snA1 = d_sin[sA*16 + ci + 1];
            float cB0 = d_cos[sB*16 + ci],     snB0 = d_sin[sB*16 + ci];
            float cB1 = d_cos[sB*16 + ci + 1], snB1 = d_sin[sB*16 + ci + 1];
            float q0 = acc[mt][nt][0], q1 = acc[mt][nt][1];
            float q2 = acc[mt][nt][2], q3 = acc[mt][nt][3];
            float p0 = acc[mt][nt ^ 2][0], p1 = acc[mt][nt ^ 2][1];
            float p2 = acc[mt][nt ^ 2][2], p3 = acc[mt][nt ^ 2][3];
            long long baseA = (((long long)(nA * 8 + h) << Sbits) + sA) * 32 + rr;
            long long baseB = (((long long)(nB * 8 + h) << Sbits) + sB) * 32 + rr;
            if (!isQV) {
                float2 w;
                w.x = q0*cA0 + sgn*p0*snA0; w.y = q1*cA1 + sgn*p1*snA1;
                *reinterpret_cast<float2*>(&OUR[baseA]) = w;
                w.x = q0*cA0 - sgn*p0*snA0; w.y = q1*cA1 - sgn*p1*snA1;
                *reinterpret_cast<float2*>(&OUO[baseA]) = w;
                w.x = q2*cB0 + sgn*p2*snB0; w.y = q3*cB1 + sgn*p3*snB1;
                *reinterpret_cast<float2*>(&OUR[baseB]) = w;
                w.x = q2*cB0 - sgn*p2*snB0; w.y = q3*cB1 - sgn*p3*snB1;
                *reinterpret_cast<float2*>(&OUO[baseB]) = w;
            } else {
                float2 w;
                w.x = q0*cA0 + sgn*p0*snA0; w.y = q1*cA1 + sgn*p1*snA1;
                *reinterpret_cast<float2*>(&OVR[baseA]) = w;
                w.x = q2*cB0 + sgn*p2*snB0; w.y = q3*cB1 + sgn*p3*snB1;
                *reinterpret_cast<float2*>(&OVR[baseB]) = w;
            }
        }
    }
}

// ---------------- final GEMM (HMMA, cp.async pipeline) ---------------------
__global__ __launch_bounds__(256, 1) void k_final_mma(float* __restrict__ out, int branch) {
    extern __shared__ char smem[];
    const int tid = threadIdx.x;
    const u32 sbase = (u32)__cvta_generic_to_shared(smem);
    const int n0 = blockIdx.x * 128;
    const int m0 = blockIdx.y * 128;
    const int lane = tid & 31, warp = tid >> 5;
    const int wm = warp >> 1, wn = warp & 1;
    const __nv_bfloat16* G0 = branch ? d_ga0_c : d_ga0_t;
    const __nv_bfloat16* G1 = branch ? d_ga1_c : d_ga1_t;
    const __nv_bfloat16* F0 = branch ? d_wf_c[0] : d_wf_t[0];
    const __nv_bfloat16* F1 = branch ? d_wf_c[1] : d_wf_t[1];

    float acc[2][8][4];
#pragma unroll
    for (int mt = 0; mt < 2; mt++)
#pragma unroll
        for (int nt = 0; nt < 8; nt++)
#pragma unroll
            for (int e = 0; e < 4; e++) acc[mt][nt][e] = 0.f;

#pragma unroll 1
    for (int kc = -1; kc < 16; kc++) {
        int ld = kc + 1;
        if (ld < 16) {
            u32 stb = sbase + (u32)(ld & 1) * (4*TILE_BYTES);
#pragma unroll
            for (int t = 0; t < 8; t++) {
                int li = tid + t * 256;
                int seg = li & 3, row = (li >> 2) & 127, tile = li >> 9;
                const __nv_bfloat16* src;
                if (tile == 0)      src = G0 + (long long)(m0 + row) * 512 + ld * 32 + seg * 8;
                else if (tile == 1) src = G1 + (long long)(m0 + row) * 512 + ld * 32 + seg * 8;
                else if (tile == 2) src = F0 + (long long)(n0 + row) * 512 + ld * 32 + seg * 8;
                else                src = F1 + (long long)(n0 + row) * 512 + ld * 32 + seg * 8;
                cpa(stb + (u32)(tile * TILE_BYTES + row * 80 + seg * 16), src);
            }
            cpa_commit();
        }
        if (kc < 0) continue;
        if (kc < 15) cpa_wait1(); else cpa_wait0();
        __syncthreads();
        u32 stb = sbase + (u32)(kc & 1) * (4*TILE_BYTES);
#pragma unroll
        for (int ks = 0; ks < 2; ks++) {
            u32 afr[2][2][4];
#pragma unroll
            for (int sp = 0; sp < 2; sp++)
#pragma unroll
                for (int mt = 0; mt < 2; mt++) {
                    u32 addr = stb + sp * TILE_BYTES
                             + (wm * 32 + mt * 16 + (lane & 15)) * 80
                             + ks * 32 + (lane >> 4) * 16;
                    ldm_x4(afr[sp][mt], addr);
                }
#pragma unroll
            for (int sb = 0; sb < 2; sb++) {
                u32 bfr[8][2];
#pragma unroll
                for (int g = 0; g < 4; g++) {
                    u32 tr[4];
                    u32 addr = stb + (2 + sb) * TILE_BYTES
                             + (wn * 64 + g * 16 + (lane & 15)) * 80
                             + ks * 32 + (lane >> 4) * 16;
                    ldm_x4(tr, addr);
                    bfr[2*g][0] = tr[0];   bfr[2*g][1] = tr[2];
                    bfr[2*g+1][0] = tr[1]; bfr[2*g+1][1] = tr[3];
                }
                int na = 2 - sb;
#pragma unroll
                for (int sa = 0; sa < 2; sa++) {
                    if (sa < na) {
#pragma unroll
                        for (int mt = 0; mt < 2; mt++)
#pragma unroll
                            for (int nt = 0; nt < 8; nt++)
                                mma_bf16(acc[mt][nt], afr[sa][mt], bfr[nt]);
                    }
                }
            }
        }
        __syncthreads();
    }
#pragma unroll
    for (int mt = 0; mt < 2; mt++)
#pragma unroll
        for (int nt = 0; nt < 8; nt++) {
            int r = m0 + wm * 32 + mt * 16 + (lane >> 2);
            int c = n0 + wn * 64 + nt * 8 + (lane & 3) * 2;
            long long r0o, r1o;
            if (!branch) {
                r0o = (long long)r; r1o = (long long)(r + 8);
            } else {
                int nn = r >> 5, cc2 = r & 31;
                int b = nn >> 7, p = nn & 127;
                r0o = (long long)((b * 32 + cc2) * 128 + p);
                int r8 = r + 8;
                nn = r8 >> 5; cc2 = r8 & 31; b = nn >> 7; p = nn & 127;
                r1o = (long long)((b * 32 + cc2) * 128 + p);
            }
            float2 lo; lo.x = acc[mt][nt][0]; lo.y = acc[mt][nt][1];
            float2 hi; hi.x = acc[mt][nt][2]; hi.y = acc[mt][nt][3];
            *reinterpret_cast<float2*>(&out[r0o * 256 + c]) = lo;
            *reinterpret_cast<float2*>(&out[r1o * 256 + c]) = hi;
        }
}

// ---------------- F_t -------------------------------------------------------
__global__ __launch_bounds__(256) void k_ft(const float* __restrict__ mask) {
    __shared__ float SuT[32][132];
    __shared__ float SvT[32][132];
    int nh = blockIdx.x;
    int n = nh >> 3;
    const float* ubase = d_qur_t + nh*128*32;
    const float* vbase = d_qvr_t + nh*128*32;
    int tid = threadIdx.x;
#pragma unroll
    for (int l = 0; l < 4; l++) {
        int lin = tid + l*256;
        int s = lin >> 3, rq = (lin & 7) << 2;
        float4 u = *reinterpret_cast<const float4*>(ubase + s*32 + rq);
        SuT[rq][s] = u.x; SuT[rq+1][s] = u.y; SuT[rq+2][s] = u.z; SuT[rq+3][s] = u.w;
        float4 v = *reinterpret_cast<const float4*>(vbase + s*32 + rq);
        SvT[rq][s] = v.x; SvT[rq+1][s] = v.y; SvT[rq+2][s] = v.z; SvT[rq+3][s] = v.w;
    }
    __syncthreads();
    int tx = tid & 15, ty = tid >> 4;
    float acc[8][8];
#pragma unroll
    for (int i = 0; i < 8; i++)
#pragma unroll
        for (int j = 0; j < 8; j++) acc[i][j] = 0.f;
#pragma unroll
    for (int k = 0; k < 32; k++) {
        float a[8], b[8];
        *(float4*)&a[0] = *(const float4*)&SuT[k][ty*8];
        *(float4*)&a[4] = *(const float4*)&SuT[k][ty*8+4];
        *(float4*)&b[0] = *(const float4*)&SvT[k][tx*8];
        *(float4*)&b[4] = *(const float4*)&SvT[k][tx*8+4];
#pragma unroll
        for (int i = 0; i < 8; i++)
#pragma unroll
            for (int j = 0; j < 8; j++) acc[i][j] += a[i]*b[j];
    }
    float* fout = d_F_t + (long long)nh*16384;
    const float* mrow = mask + (long long)n*16384;
#pragma unroll
    for (int i = 0; i < 8; i++) {
        int s = ty*8 + i;
#pragma unroll
        for (int j4 = 0; j4 < 2; j4++) {
            int t = tx*8 + j4*4;
            float4 m4 = *reinterpret_cast<const float4*>(mrow + s*128 + t);
            float4 o;
            o.x = acc[i][j4*4]   + m4.x;
            o.y = acc[i][j4*4+1] + m4.y;
            o.z = acc[i][j4*4+2] + m4.z;
            o.w = acc[i][j4*4+3] + m4.w;
            *reinterpret_cast<float4*>(fout + s*128 + t) = o;
        }
    }
}

// ---------------- F_c -------------------------------------------------------
__global__ __launch_bounds__(256) void k_fc(const float* __restrict__ mask) {
    __shared__ float SuT[32][36];
    __shared__ float SvT[32][36];
    int nh = blockIdx.x;
    int n = nh >> 3;
    const float* ubase = d_qur_c + nh*1024;
    const float* vbase = d_qvr_c + nh*1024;
    int tid = threadIdx.x;
    {
        int s = tid >> 3, rq = (tid & 7) << 2;
        float4 u = *reinterpret_cast<const float4*>(ubase + s*32 + rq);
        SuT[rq][s] = u.x; SuT[rq+1][s] = u.y; SuT[rq+2][s] = u.z; SuT[rq+3][s] = u.w;
        float4 v = *reinterpret_cast<const float4*>(vbase + s*32 + rq);
        SvT[rq][s] = v.x; SvT[rq+1][s] = v.y; SvT[rq+2][s] = v.z; SvT[rq+3][s] = v.w;
    }
    __syncthreads();
    int tx = tid & 7, ty = tid >> 3;
    float acc[4];
    acc[0] = 0.f; acc[1] = 0.f; acc[2] = 0.f; acc[3] = 0.f;
#pragma unroll
    for (int k = 0; k < 32; k++) {
        float a = SuT[k][ty];
        float4 b = *(const float4*)&SvT[k][tx*4];
        acc[0] += a*b.x; acc[1] += a*b.y; acc[2] += a*b.z; acc[3] += a*b.w;
    }
    int t0 = tx*4;
    float4 m4 = *reinterpret_cast<const float4*>(mask + (long long)n*1024 + ty*32 + t0);
    float4 o;
    o.x = acc[0] + m4.x; o.y = acc[1] + m4.y; o.z = acc[2] + m4.z; o.w = acc[3] + m4.w;
    *reinterpret_cast<float4*>(d_F_c + (long long)nh*1024 + ty*32 + t0) = o;
}

// ---------------- joint softmax --------------------------------------------
__global__ __launch_bounds__(256) void k_softmax() {
    int warp = threadIdx.x >> 5, lane = threadIdx.x & 31;
    int rowid = blockIdx.x * 8 + warp;
    int p  = rowid & 127;
    int r1 = rowid >> 7;
    int c  = r1 & 31;
    int r2 = r1 >> 5;
    int h  = r2 & 7;
    int b  = r2 >> 3;
    float* ft = d_F_t + ((long long)(((b*32 + c)*8 + h)*128 + p))*128;
    float* fc = d_F_c + ((long long)(((b*128 + p)*8 + h)*32 + c))*32;
    float v[5];
    v[0] = ft[lane]; v[1] = ft[lane+32]; v[2] = ft[lane+64]; v[3] = ft[lane+96];
    v[4] = fc[lane];
    float m = v[0];
#pragma unroll
    for (int i = 1; i < 5; i++) m = fmaxf(m, v[i]);
#pragma unroll
    for (int off = 16; off >= 1; off >>= 1)
        m = fmaxf(m, __shfl_xor_sync(0xffffffffu, m, off));
    float sum = 0.f;
#pragma unroll
    for (int i = 0; i < 5; i++) { v[i] = expf(256.f*(v[i] - m)); sum += v[i]; }
#pragma unroll
    for (int off = 16; off >= 1; off >>= 1)
        sum += __shfl_xor_sync(0xffffffffu, sum, off);
    float inv = 1.f / sum;
    ft[lane]     = v[0]*inv;
    ft[lane+32]  = v[1]*inv;
    ft[lane+64]  = v[2]*inv;
    ft[lane+96]  = v[3]*inv;
    fc[lane]     = v[4]*inv;
}

// ---------------- G time ----------------------------------------------------
__global__ __launch_bounds__(256) void k_gt() {
    __shared__ float Qa[32][132];
    __shared__ float Qb[32][132];
    __shared__ float Vs[32][34];
    __shared__ float Us[32][34];
    int nh = blockIdx.x;
    int n = nh >> 3, h = nh & 7;
    const float* qh = d_F_t + (long long)nh*16384;
    const float* vb = d_qvr_t + nh*4096;
    const float* ub = d_quo_t + nh*4096;
    int tid = threadIdx.x;
    int rg = tid & 7, sg = tid >> 3;
    float a1[4][4], a2[4][4];
#pragma unroll
    for (int i = 0; i < 4; i++)
#pragma unroll
        for (int j = 0; j < 4; j++) { a1[i][j] = 0.f; a2[i][j] = 0.f; }

    for (int t0 = 0; t0 < 128; t0 += 32) {
        __syncthreads();
#pragma unroll
        for (int l = 0; l < 4; l++) {
            int lin = tid + l*256;
            int s = lin >> 3, iq = (lin & 7) << 2;
            float4 q = *(const float4*)(qh + s*128 + t0 + iq);
            Qa[iq][s] = q.x; Qa[iq+1][s] = q.y; Qa[iq+2][s] = q.z; Qa[iq+3][s] = q.w;
        }
#pragma unroll
        for (int l = 0; l < 4; l++) {
            int lin = tid + l*256;
            int i = lin >> 5, sq = (lin & 31) << 2;
            float4 q = *(const float4*)(qh + (t0 + i)*128 + sq);
            *(float4*)&Qb[i][sq] = q;
        }
        {
            int i = tid >> 3, rq = (tid & 7) << 2;
            float4 v = *(const float4*)(vb + (t0 + i)*32 + rq);
            Vs[i][rq] = v.x; Vs[i][rq+1] = v.y; Vs[i][rq+2] = v.z; Vs[i][rq+3] = v.w;
            float4 u = *(const float4*)(ub + (t0 + i)*32 + rq);
            Us[i][rq] = u.x; Us[i][rq+1] = u.y; Us[i][rq+2] = u.z; Us[i][rq+3] = u.w;
        }
        __syncthreads();
#pragma unroll
        for (int i = 0; i < 32; i++) {
            float4 qa = *(const float4*)&Qa[i][sg*4];
            float4 qb = *(const float4*)&Qb[i][sg*4];
            float2 v0 = *(const float2*)&Vs[i][rg*2];
            float2 v1 = *(const float2*)&Vs[i][rg*2+16];
            float2 u0 = *(const float2*)&Us[i][rg*2];
            float2 u1 = *(const float2*)&Us[i][rg*2+16];
            float av[4], bv[4], vv[4], uv[4];
            av[0] = qa.x; av[1] = qa.y; av[2] = qa.z; av[3] = qa.w;
            bv[0] = qb.x; bv[1] = qb.y; bv[2] = qb.z; bv[3] = qb.w;
            vv[0] = v0.x; vv[1] = v0.y; vv[2] = v1.x; vv[3] = v1.y;
            uv[0] = u0.x; uv[1] = u0.y; uv[2] = u1.x; uv[3] = u1.y;
#pragma unroll
            for (int si = 0; si < 4; si++)
#pragma unroll
                for (int rj = 0; rj < 4; rj++) {
                    a1[si][rj] += av[si]*vv[rj];
                    a2[si][rj] += bv[si]*uv[rj];
                }
        }
    }
#pragma unroll
    for (int si = 0; si < 4; si++) {
        int s = sg*4 + si;
        long long rb = (long long)(n*128 + s) * 512;
#pragma unroll
        for (int rj = 0; rj < 2; rj++) {
            int r = rg*2 + rj;
            float c  = d_cos[s*16 + r];
            float sn = d_sin[s*16 + r];
            float xl = a1[si][rj], xh = a1[si][rj+2];
            float yl = a2[si][rj], yh = a2[si][rj+2];
            int col = h*32 + r;
            st_split(d_ga0_t, d_ga1_t, rb + col,        xl*c + xh*sn);
            st_split(d_ga0_t, d_ga1_t, rb + col + 16,   xh*c - xl*sn);
            st_split(d_ga0_t, d_ga1_t, rb + 256 + col,      yl*c - yh*sn);
            st_split(d_ga0_t, d_ga1_t, rb + 256 + col + 16, yh*c + yl*sn);
        }
    }
}

// ---------------- G chan ----------------------------------------------------
__global__ __launch_bounds__(128) void k_gc() {
    __shared__ float Qn[32][34];
    __shared__ float Vs[32][34];
    __shared__ float Us[32][34];
    int nh = blockIdx.x;
    int n = nh >> 3, h = nh & 7;
    const float* qh = d_F_c + (long long)nh*1024;
    const float* vb = d_qvr_c + nh*1024;
    const float* ub = d_quo_c + nh*1024;
    int tid = threadIdx.x;
#pragma unroll
    for (int l = 0; l < 2; l++) {
        int lin = tid + l*128;
        int t = lin >> 3, sq = (lin & 7) << 2;
        float4 q = *(const float4*)(qh + t*32 + sq);
        Qn[t][sq] = q.x; Qn[t][sq+1] = q.y; Qn[t][sq+2] = q.z; Qn[t][sq+3] = q.w;
        float4 v = *(const float4*)(vb + t*32 + sq);
        Vs[t][sq] = v.x; Vs[t][sq+1] = v.y; Vs[t][sq+2] = v.z; Vs[t][sq+3] = v.w;
        float4 u = *(const float4*)(ub + t*32 + sq);
        Us[t][sq] = u.x; Us[t][sq+1] = u.y; Us[t][sq+2] = u.z; Us[t][sq+3] = u.w;
    }
    __syncthreads();
    int rg = tid & 7, sg = tid >> 3;
    float a1[2][4], a2[2][4];
#pragma unroll
    for (int i = 0; i < 2; i++)
#pragma unroll
        for (int j = 0; j < 4; j++) { a1[i][j] = 0.f; a2[i][j] = 0.f; }
#pragma unroll
    for (int t = 0; t < 32; t++) {
        float av[2], bv[2], vv[4], uv[4];
        av[0] = Qn[sg*2][t];
        av[1] = Qn[sg*2+1][t];
        float2 qb = *(const float2*)&Qn[t][sg*2];
        float2 v0 = *(const float2*)&Vs[t][rg*2];
        float2 v1 = *(const float2*)&Vs[t][rg*2+16];
        float2 u0 = *(const float2*)&Us[t][rg*2];
        float2 u1 = *(const float2*)&Us[t][rg*2+16];
        bv[0] = qb.x; bv[1] = qb.y;
        vv[0] = v0.x; vv[1] = v0.y; vv[2] = v1.x; vv[3] = v1.y;
        uv[0] = u0.x; uv[1] = u0.y; uv[2] = u1.x; uv[3] = u1.y;
#pragma unroll
        for (int si = 0; si < 2; si++)
#pragma unroll
            for (int rj = 0; rj < 4; rj++) {
                a1[si][rj] += av[si]*vv[rj];
                a2[si][rj] += bv[si]*uv[rj];
            }
    }
#pragma unroll
    for (int si = 0; si < 2; si++) {
        int s = sg*2 + si;
        long long rb = (long long)(n*32 + s) * 512;
#pragma unroll
        for (int rj = 0; rj < 2; rj++) {
            int r = rg*2 + rj;
            float c  = d_cos[s*16 + r];
            float sn = d_sin[s*16 + r];
            float xl = a1[si][rj], xh = a1[si][rj+2];
            float yl = a2[si][rj], yh = a2[si][rj+2];
            int col = h*32 + r;
            st_split(d_ga0_c, d_ga1_c, rb + col,        xl*c + xh*sn);
            st_split(d_ga0_c, d_ga1_c, rb + col + 16,   xh*c - xl*sn);
            st_split(d_ga0_c, d_ga1_c, rb + 256 + col,      yl*c - yh*sn);
            st_split(d_ga0_c, d_ga1_c, rb + 256 + col + 16, yh*c + yl*sn);
        }
    }
}

// ---------------- launch ---------------------------------------------------
extern "C" void kernel_launch(void* const* d_in, const int* in_sizes, int n_in,
                              void* d_out, int out_size)
{
    const float* qz = (const float*)d_in[0];
    const float* mask_t = (const float*)d_in[1];
    const float* mask_c = (const float*)d_in[2];
    const float* u_t = (const float*)d_in[3];
    const float* v_t = (const float*)d_in[4];
    const float* u_c = (const float*)d_in[5];
    const float* v_c = (const float*)d_in[6];
    float* out = (float*)d_out;

    cudaFuncSetAttribute(k_proj_mma, cudaFuncAttributeMaxDynamicSharedMemorySize, PROJ_SMEM);
    cudaFuncSetAttribute(k_final_mma, cudaFuncAttributeMaxDynamicSharedMemorySize, FIN_SMEM);

    k_setup<<<8, 256>>>();
    k_split_qz<<<8192, 256>>>(qz);
    k_split_w<<<512, 256>>>(u_t, v_t, 0);
    k_split_w<<<512, 256>>>(u_c, v_c, 1);
    k_split_wf<<<512, 256>>>(u_t, v_t, 0);
    k_split_wf<<<512, 256>>>(u_c, v_c, 1);

    k_proj_mma<<<dim3(4, 256), 256, PROJ_SMEM>>>(0);
    k_proj_mma<<<dim3(4, 256), 256, PROJ_SMEM>>>(1);

    k_ft<<<NT*HH, 256>>>(mask_t);
    k_fc<<<NC*HH, 256>>>(mask_c);

    k_softmax<<<32768, 256>>>();

    k_gt<<<NT*HH, 256>>>();
    k_gc<<<NC*HH, 128>>>();

    k_final_mma<<<dim3(2, 256), 256, FIN_SMEM>>>(out, 0);
    k_final_mma<<<dim3(2, 256), 256, FIN_SMEM>>>(out + OUT_HALF, 1);
}